// round 5
// baseline (speedup 1.0000x reference)
#include <cuda_runtime.h>
#include <math.h>

#define BB 4
#define SS 2048
#define DD 512
#define HH 8
#define HD 64
#define BH (BB*HH)

// Scratch (device globals — no allocation allowed)
__device__ float    g_q[BH * SS * HD];      // [b,h,s,hd] fp32
__device__ float    g_k[BH * SS * HD];
__device__ float    g_v[BH * SS * HD];
__device__ float    g_x[BB * SS * DD];      // [b,s,h*hd] attn out before Wo
__device__ unsigned g_mbits[BB * SS * (SS/32)]; // bit-packed mask

// ---------------------------------------------------------------------------
__device__ __forceinline__ unsigned f2tf(float x) {
    unsigned r;
    asm("cvt.rna.tf32.f32 %0, %1;" : "=r"(r) : "f"(x));
    return r;
}

__device__ __forceinline__ void mma_tf32(float c[4], const unsigned a[4], const unsigned b[2]) {
    asm volatile(
        "mma.sync.aligned.m16n8k8.row.col.f32.tf32.tf32.f32 "
        "{%0,%1,%2,%3},{%4,%5,%6,%7},{%8,%9},{%0,%1,%2,%3};"
        : "+f"(c[0]), "+f"(c[1]), "+f"(c[2]), "+f"(c[3])
        : "r"(a[0]), "r"(a[1]), "r"(a[2]), "r"(a[3]), "r"(b[0]), "r"(b[1]));
}

__device__ __forceinline__ void cp16(void* dst_smem, const void* src_gmem) {
    unsigned d = (unsigned)__cvta_generic_to_shared(dst_smem);
    asm volatile("cp.async.cg.shared.global [%0], [%1], 16;" :: "r"(d), "l"(src_gmem));
}
#define CP_COMMIT()  asm volatile("cp.async.commit_group;")
#define CP_WAIT(n)   asm volatile("cp.async.wait_group %0;" :: "n"(n))

// ---------------------------------------------------------------------------
__global__ __launch_bounds__(256) void pack_mask_kernel(
    const int* __restrict__ mask, unsigned* __restrict__ bits)
{
    int w = blockIdx.x * 256 + threadIdx.x;
    const int4* p = (const int4*)(mask + (size_t)w * 32);
    unsigned v = 0;
    #pragma unroll
    for (int i = 0; i < 8; i++) {
        int4 q = p[i];
        v |= (unsigned)(q.x != 0) << (i * 4 + 0);
        v |= (unsigned)(q.y != 0) << (i * 4 + 1);
        v |= (unsigned)(q.z != 0) << (i * 4 + 2);
        v |= (unsigned)(q.w != 0) << (i * 4 + 3);
    }
    bits[w] = v;
}

// ---------------------------------------------------------------------------
// Projection GEMM: C = X @ W^T + bias. Block 256x128, 512 threads (16 warps,
// 4m x 4n, warp 64x32). Raw fp32 smem via cp.async double-buffer, tf32 cvt
// at fragment load. k-tile = 16.
// ---------------------------------------------------------------------------
__device__ __forceinline__ void proj_issue(
    float* Ab, float* Bb, const float* X, const float* W,
    int m0, int n0, int kb, int t)
{
    #pragma unroll
    for (int i = 0; i < 2; i++) {
        int id = i * 512 + t;
        int r = id >> 2, c4 = (id & 3) * 4;
        cp16(Ab + r * 20 + c4, X + (size_t)(m0 + r) * DD + kb + c4);
    }
    {
        int r = t >> 2, c4 = (t & 3) * 4;
        cp16(Bb + r * 20 + c4, W + (size_t)(n0 + r) * DD + kb + c4);
    }
    CP_COMMIT();
}

__global__ __launch_bounds__(512) void proj_mma(
    const float* __restrict__ X, const float* __restrict__ W,
    const float* __restrict__ bias, float* __restrict__ out, int scatter)
{
    extern __shared__ float psm[];
    float* Abuf[2] = { psm, psm + 5120 };          // [256][20]
    float* Bbuf[2] = { psm + 10240, psm + 12800 }; // [128][20]

    const int t = threadIdx.x;
    const int warp = t >> 5, lane = t & 31;
    const int wm = warp >> 2, wn = warp & 3;       // 4 x 4
    const int g = lane >> 2, tig = lane & 3;
    const int m0 = blockIdx.y * 256, n0 = blockIdx.x * 128;

    float acc[4][4][4] = {};

    proj_issue(Abuf[0], Bbuf[0], X, W, m0, n0, 0, t);

    for (int kt = 0; kt < 32; kt++) {
        __syncthreads();
        proj_issue(Abuf[(kt + 1) & 1], Bbuf[(kt + 1) & 1], X, W, m0, n0,
                   ((kt + 1) & 31) * 16, t);
        CP_WAIT(1);
        __syncthreads();
        const float* Ac = Abuf[kt & 1];
        const float* Bc = Bbuf[kt & 1];

        #pragma unroll
        for (int kk = 0; kk < 16; kk += 8) {
            unsigned af[4][4], bf[4][2];
            #pragma unroll
            for (int mt = 0; mt < 4; mt++) {
                int mrow = wm * 64 + mt * 16;
                af[mt][0] = f2tf(Ac[(mrow + g) * 20 + kk + tig]);
                af[mt][1] = f2tf(Ac[(mrow + g + 8) * 20 + kk + tig]);
                af[mt][2] = f2tf(Ac[(mrow + g) * 20 + kk + tig + 4]);
                af[mt][3] = f2tf(Ac[(mrow + g + 8) * 20 + kk + tig + 4]);
            }
            #pragma unroll
            for (int nt = 0; nt < 4; nt++) {
                int ncol = wn * 32 + nt * 8 + g;
                bf[nt][0] = f2tf(Bc[ncol * 20 + kk + tig]);
                bf[nt][1] = f2tf(Bc[ncol * 20 + kk + tig + 4]);
            }
            #pragma unroll
            for (int mt = 0; mt < 4; mt++)
                #pragma unroll
                for (int nt = 0; nt < 4; nt++)
                    mma_tf32(acc[mt][nt], af[mt], bf[nt]);
        }
    }
    CP_WAIT(0);

    #pragma unroll
    for (int nt = 0; nt < 4; nt++) {
        const int col = n0 + wn * 32 + nt * 8 + 2 * tig;
        const float b0v = bias[col], b1v = bias[col + 1];
        #pragma unroll
        for (int mt = 0; mt < 4; mt++) {
            #pragma unroll
            for (int half = 0; half < 2; half++) {
                int m = m0 + wm * 64 + mt * 16 + g + half * 8;
                float2 v;
                v.x = acc[mt][nt][half * 2 + 0] + b0v;
                v.y = acc[mt][nt][half * 2 + 1] + b1v;
                if (scatter) {
                    int b = m >> 11, s = m & (SS - 1);
                    int h = col >> 6, hd = col & (HD - 1);
                    *(float2*)&out[(((size_t)(b * HH + h)) * SS + s) * HD + hd] = v;
                } else {
                    *(float2*)&out[(size_t)m * DD + col] = v;
                }
            }
        }
    }
}

// ---------------------------------------------------------------------------
// Fused attention, two-phase with cp.async pipelining.
// smem words: Qs[128*68] tf32 | Kb 2x[128*68] raw | Vs[128*72] raw |
//             Ps[128*132] tf32 | rowsum[128]
// ---------------------------------------------------------------------------
#define QS_OFF   0
#define KB_OFF   8704
#define VS_OFF   26112
#define PS_OFF   35328
#define RS_OFF   52224
#define ATTN_SMEM_W 52352

__device__ __forceinline__ void attn_issue_K(float* kbuf, const float* kg, int n0, int t)
{
    #pragma unroll
    for (int i = 0; i < 8; i++) {
        int id = i * 256 + t;
        int r = id >> 4, c4 = (id & 15) * 4;
        cp16(kbuf + r * 68 + c4, kg + (size_t)(n0 + r) * HD + c4);
    }
    CP_COMMIT();
}

__device__ __forceinline__ void attn_issue_V(float* vbuf, const float* vg, int n0, int t)
{
    #pragma unroll
    for (int i = 0; i < 8; i++) {
        int id = i * 256 + t;
        int r = id >> 4, c4 = (id & 15) * 4;
        cp16(vbuf + r * 72 + c4, vg + (size_t)(n0 + r) * HD + c4);
    }
    CP_COMMIT();
}

__global__ __launch_bounds__(256) void attn_fused(float* __restrict__ dist)
{
    extern __shared__ float sm[];
    unsigned* Qs = (unsigned*)(sm + QS_OFF);
    float* Kb[2] = { sm + KB_OFF, sm + KB_OFF + 8704 };
    float* Vs    = sm + VS_OFF;
    unsigned* Ps = (unsigned*)(sm + PS_OFF);
    float* rowsum = sm + RS_OFF;

    const int t = threadIdx.x;
    const int warp = t >> 5, lane = t & 31;
    const int wm = warp >> 2, wn = warp & 3;       // scores: 2m x 4n (warp 64x32)
    const int wm2 = warp >> 1, wn2 = warp & 1;     // PV:     4m x 2n (warp 32x32)
    const int g = lane >> 2, tig = lane & 3;
    const int bh = blockIdx.y, b = bh >> 3, h = bh & 7;
    const int m0 = blockIdx.x * 128;

    const float* q = g_q + (size_t)bh * SS * HD;
    const float* k = g_k + (size_t)bh * SS * HD;
    const float* v = g_v + (size_t)bh * SS * HD;

    // prologue: K tile 0 in flight; load+convert Q; zero rowsum
    attn_issue_K(Kb[0], k, 0, t);
    #pragma unroll
    for (int i = 0; i < 8; i++) {
        int f = i * 256 + t;
        int r = f >> 4, c4 = (f & 15) * 4;
        float4 qv = *(const float4*)&q[(size_t)(m0 + r) * HD + c4];
        *(uint4*)&Qs[r * 68 + c4] = make_uint4(f2tf(qv.x), f2tf(qv.y), f2tf(qv.z), f2tf(qv.w));
    }
    if (t < 128) rowsum[t] = 0.0f;

    float rs[4][2] = {};

    // ======== Phase A: row sums ========
    for (int it = 0; it < 16; it++) {
        __syncthreads();
        attn_issue_K(Kb[(it + 1) & 1], k, ((it + 1) & 15) * 128, t);
        CP_WAIT(1);
        __syncthreads();
        const float* Kc = Kb[it & 1];
        const int n0 = it * 128;

        float acc[4][4][4] = {};
        #pragma unroll
        for (int kk = 0; kk < 64; kk += 8) {
            unsigned af[4][4], bf[4][2];
            #pragma unroll
            for (int mt = 0; mt < 4; mt++) {
                int mrow = wm * 64 + mt * 16;
                af[mt][0] = Qs[(mrow + g) * 68 + kk + tig];
                af[mt][1] = Qs[(mrow + g + 8) * 68 + kk + tig];
                af[mt][2] = Qs[(mrow + g) * 68 + kk + tig + 4];
                af[mt][3] = Qs[(mrow + g + 8) * 68 + kk + tig + 4];
            }
            #pragma unroll
            for (int nt = 0; nt < 4; nt++) {
                int ncol = wn * 32 + nt * 8 + g;
                bf[nt][0] = f2tf(Kc[ncol * 68 + kk + tig]);
                bf[nt][1] = f2tf(Kc[ncol * 68 + kk + tig + 4]);
            }
            #pragma unroll
            for (int mt = 0; mt < 4; mt++)
                #pragma unroll
                for (int nt = 0; nt < 4; nt++)
                    mma_tf32(acc[mt][nt], af[mt], bf[nt]);
        }

        #pragma unroll
        for (int mt = 0; mt < 4; mt++) {
            #pragma unroll
            for (int half = 0; half < 2; half++) {
                int row = m0 + wm * 64 + mt * 16 + g + half * 8;
                unsigned mb = g_mbits[((size_t)b * SS + row) * (SS/32) + (n0 >> 5) + wn];
                #pragma unroll
                for (int nt = 0; nt < 4; nt++) {
                    int nloc = nt * 8 + 2 * tig;
                    float e0 = ((mb >> nloc) & 1u) ? 0.0f : __expf(acc[mt][nt][half*2+0] * 0.125f);
                    float e1 = ((mb >> (nloc+1)) & 1u) ? 0.0f : __expf(acc[mt][nt][half*2+1] * 0.125f);
                    rs[mt][half] += e0 + e1;
                }
            }
        }
    }

    // reduce row sums, invert
    #pragma unroll
    for (int mt = 0; mt < 4; mt++)
        #pragma unroll
        for (int half = 0; half < 2; half++) {
            float s = rs[mt][half];
            s += __shfl_xor_sync(0xffffffffu, s, 1);
            s += __shfl_xor_sync(0xffffffffu, s, 2);
            if (tig == 0)
                atomicAdd(&rowsum[wm * 64 + mt * 16 + g + half * 8], s);
        }
    __syncthreads();
    if (t < 128) rowsum[t] = 1.0f / rowsum[t];

    // ======== Phase B: recompute, write normalized dist, PV ========
    float y[2][4][4] = {};
    const size_t dbase = (size_t)bh * SS * SS;

    attn_issue_V(Vs, v, 0, t);

    for (int it = 0; it < 16; it++) {
        CP_WAIT(1);              // K(it) ready (V(it) may be pending)
        __syncthreads();         // also publishes rowsum inversion on it==0
        const float* Kc = Kb[it & 1];
        const int n0 = it * 128;

        float acc[4][4][4] = {};
        #pragma unroll
        for (int kk = 0; kk < 64; kk += 8) {
            unsigned af[4][4], bf[4][2];
            #pragma unroll
            for (int mt = 0; mt < 4; mt++) {
                int mrow = wm * 64 + mt * 16;
                af[mt][0] = Qs[(mrow + g) * 68 + kk + tig];
                af[mt][1] = Qs[(mrow + g + 8) * 68 + kk + tig];
                af[mt][2] = Qs[(mrow + g) * 68 + kk + tig + 4];
                af[mt][3] = Qs[(mrow + g + 8) * 68 + kk + tig + 4];
            }
            #pragma unroll
            for (int nt = 0; nt < 4; nt++) {
                int ncol = wn * 32 + nt * 8 + g;
                bf[nt][0] = f2tf(Kc[ncol * 68 + kk + tig]);
                bf[nt][1] = f2tf(Kc[ncol * 68 + kk + tig + 4]);
            }
            #pragma unroll
            for (int mt = 0; mt < 4; mt++)
                #pragma unroll
                for (int nt = 0; nt < 4; nt++)
                    mma_tf32(acc[mt][nt], af[mt], bf[nt]);
        }

        attn_issue_K(Kb[(it + 1) & 1], k, ((it + 1) & 15) * 128, t);

        // epilogue: normalize, write final dist, deposit tf32 P
        #pragma unroll
        for (int mt = 0; mt < 4; mt++) {
            #pragma unroll
            for (int half = 0; half < 2; half++) {
                int rowl = wm * 64 + mt * 16 + g + half * 8;
                int row = m0 + rowl;
                unsigned mb = g_mbits[((size_t)b * SS + row) * (SS/32) + (n0 >> 5) + wn];
                float inv = rowsum[rowl];
                #pragma unroll
                for (int nt = 0; nt < 4; nt++) {
                    int nloc = nt * 8 + 2 * tig;
                    float e0 = ((mb >> nloc) & 1u) ? 0.0f : __expf(acc[mt][nt][half*2+0] * 0.125f) * inv;
                    float e1 = ((mb >> (nloc+1)) & 1u) ? 0.0f : __expf(acc[mt][nt][half*2+1] * 0.125f) * inv;
                    float2 ev; ev.x = e0; ev.y = e1;
                    *(float2*)&dist[dbase + (size_t)row * SS + n0 + wn * 32 + nloc] = ev;
                    uint2 pv; pv.x = f2tf(e0); pv.y = f2tf(e1);
                    *(uint2*)&Ps[rowl * 132 + wn * 32 + nloc] = pv;
                }
            }
        }

        CP_WAIT(1);              // V(it) ready (K(it+1) pending)
        __syncthreads();         // P visible, V visible

        // PV: y += P[128x128] @ V[128x64]; warps 4m x 2n (32x32)
        #pragma unroll
        for (int kk = 0; kk < 128; kk += 8) {
            unsigned af[2][4], bf[4][2];
            #pragma unroll
            for (int mt = 0; mt < 2; mt++) {
                int mrow = wm2 * 32 + mt * 16;
                af[mt][0] = Ps[(mrow + g) * 132 + kk + tig];
                af[mt][1] = Ps[(mrow + g + 8) * 132 + kk + tig];
                af[mt][2] = Ps[(mrow + g) * 132 + kk + tig + 4];
                af[mt][3] = Ps[(mrow + g + 8) * 132 + kk + tig + 4];
            }
            #pragma unroll
            for (int nt = 0; nt < 4; nt++) {
                int ncol = wn2 * 32 + nt * 8 + g;
                bf[nt][0] = f2tf(Vs[(kk + tig) * 72 + ncol]);
                bf[nt][1] = f2tf(Vs[(kk + tig + 4) * 72 + ncol]);
            }
            #pragma unroll
            for (int mt = 0; mt < 2; mt++)
                #pragma unroll
                for (int nt = 0; nt < 4; nt++)
                    mma_tf32(y[mt][nt], af[mt], bf[nt]);
        }
        __syncthreads();         // P/V consumed before next overwrite
        attn_issue_V(Vs, v, ((it + 1) & 15) * 128, t);
    }
    CP_WAIT(0);

    // write attention output (already normalized via P)
    #pragma unroll
    for (int mt = 0; mt < 2; mt++) {
        #pragma unroll
        for (int nt = 0; nt < 4; nt++) {
            #pragma unroll
            for (int half = 0; half < 2; half++) {
                int row = m0 + wm2 * 32 + mt * 16 + g + half * 8;
                int col = wn2 * 32 + nt * 8 + 2 * tig;
                float2 o;
                o.x = y[mt][nt][half * 2 + 0];
                o.y = y[mt][nt][half * 2 + 1];
                *(float2*)&g_x[((size_t)(b * SS + row)) * DD + h * HD + col] = o;
            }
        }
    }
}

// ---------------------------------------------------------------------------
extern "C" void kernel_launch(void* const* d_in, const int* in_sizes, int n_in,
                              void* d_out, int out_size)
{
    const float* Q  = (const float*)d_in[0];
    const float* K  = (const float*)d_in[1];
    const float* V  = (const float*)d_in[2];
    const int*   mask = (const int*)d_in[3];
    const float* Wq = (const float*)d_in[4];
    const float* bq = (const float*)d_in[5];
    const float* Wk = (const float*)d_in[6];
    const float* bk = (const float*)d_in[7];
    const float* Wv = (const float*)d_in[8];
    const float* bv = (const float*)d_in[9];
    const float* Wo = (const float*)d_in[10];
    const float* bo = (const float*)d_in[11];

    float* out_x    = (float*)d_out;                        // [B,S,D]
    float* out_dist = (float*)d_out + (size_t)BB * SS * DD; // [B,H,S,S]

    void* pq; void* pk; void* pv; void* px; void* pbits;
    cudaGetSymbolAddress(&pq, g_q);
    cudaGetSymbolAddress(&pk, g_k);
    cudaGetSymbolAddress(&pv, g_v);
    cudaGetSymbolAddress(&px, g_x);
    cudaGetSymbolAddress(&pbits, g_mbits);

    const int PROJ_SMEM = 15360 * 4;           // 61,440 B
    const int ATTN_SMEM = ATTN_SMEM_W * 4;     // 209,408 B
    cudaFuncSetAttribute(proj_mma, cudaFuncAttributeMaxDynamicSharedMemorySize, PROJ_SMEM);
    cudaFuncSetAttribute(attn_fused, cudaFuncAttributeMaxDynamicSharedMemorySize, ATTN_SMEM);

    pack_mask_kernel<<<(BB * SS * (SS/32)) / 256, 256>>>(mask, (unsigned*)pbits);

    dim3 gproj(DD / 128, (BB * SS) / 256);                  // (4, 32) = 128 blocks
    proj_mma<<<gproj, 512, PROJ_SMEM>>>(Q, Wq, bq, (float*)pq, 1);
    proj_mma<<<gproj, 512, PROJ_SMEM>>>(K, Wk, bk, (float*)pk, 1);
    proj_mma<<<gproj, 512, PROJ_SMEM>>>(V, Wv, bv, (float*)pv, 1);

    dim3 gattn(SS / 128, BH);                               // (16, 32)
    attn_fused<<<gattn, 256, ATTN_SMEM>>>(out_dist);

    proj_mma<<<gproj, 512, PROJ_SMEM>>>((const float*)px, Wo, bo, out_x, 0);
}